// round 5
// baseline (speedup 1.0000x reference)
#include <cuda_runtime.h>
#include <cstdint>

#define C_IN   64
#define C_OUT  64
#define Hdim   224
#define Wdim   224
#define HW     (Hdim * Wdim)
#define HC     4                  // output rows per CTA
#define NTHR   256

#define WCI32  72                 // u32 stride per ci-group in weight smem (conflict-free)
#define TAPW   (16 * WCI32)       // u32 per tap block
#define WS_BYTES (9 * TAPW * 4)   // 41472
#define PXS    136                // u32 stride per ci-group in x plane (conflict-free)
#define PLANE  (16 * PXS)         // u32 per plane (h or l), 2176
#define SLOT   (2 * PLANE)        // u32 per staged row (h+l planes), 4352
#define NSLOT  4
#define X_OFF  WS_BYTES
#define SMEM_TOTAL (X_OFF + NSLOT * SLOT * 4)   // 111104 B

// ternary weights as s8 {-1,0,+1}: byte index ((tap*16 + ci/4)*64 + co)*4 + (ci&3)
__device__ unsigned char g_tb8[9 * 16 * C_OUT * 4];
__device__ float g_alpha[C_OUT];

// ---------------------------------------------------------------- ternarize
__global__ void ternarize_kernel(const float* __restrict__ weight) {
    __shared__ float red[256], red2[256];
    __shared__ float s_delta, s_alpha;
    const int co = blockIdx.x, tid = threadIdx.x;
    const float* w = weight + co * 576;

    float v0 = (tid < 576) ? w[tid] : 0.0f;
    float v1 = (tid + 256 < 576) ? w[tid + 256] : 0.0f;
    float v2 = (tid + 512 < 576) ? w[tid + 512] : 0.0f;
    float a0 = fabsf(v0), a1 = fabsf(v1), a2 = fabsf(v2);

    red[tid] = a0 + a1 + a2;
    __syncthreads();
    for (int s = 128; s > 0; s >>= 1) { if (tid < s) red[tid] += red[tid + s]; __syncthreads(); }
    if (tid == 0) s_delta = (float)(0.7 / 576.0) * red[0];
    __syncthreads();
    const float delta = s_delta;

    float m0 = (a0 > delta) ? 1.f : 0.f, m1 = (a1 > delta) ? 1.f : 0.f, m2 = (a2 > delta) ? 1.f : 0.f;
    red[tid] = m0 * a0 + m1 * a1 + m2 * a2;
    red2[tid] = m0 + m1 + m2;
    __syncthreads();
    for (int s = 128; s > 0; s >>= 1) {
        if (tid < s) { red[tid] += red[tid + s]; red2[tid] += red2[tid + s]; }
        __syncthreads();
    }
    if (tid == 0) {
        float cnt = red2[0]; if (cnt < 0.5f) cnt = 1.0f;
        s_alpha = fmaxf(red[0] / cnt, 1e-4f);
        g_alpha[co] = s_alpha;
    }
    __syncthreads();

#pragma unroll
    for (int q = 0; q < 3; q++) {
        int f = tid + q * 256;
        if (f < 576) {
            float v = (q == 0) ? v0 : (q == 1) ? v1 : v2;
            int t = (v > delta) ? 1 : ((v < -delta) ? -1 : 0);
            int ci = f / 9, tap = f % 9;       // weight layout [co][ci][kh][kw]
            g_tb8[((tap * 16 + (ci >> 2)) * C_OUT + co) * 4 + (ci & 3)] = (unsigned char)(char)t;
        }
    }
}

// ---------------------------------------------------------------- helpers
__device__ __forceinline__ void imma(int* c, const uint32_t* a, uint32_t b0, uint32_t b1) {
    asm volatile(
        "mma.sync.aligned.m16n8k32.row.col.s32.s8.s8.s32 "
        "{%0,%1,%2,%3}, {%4,%5,%6,%7}, {%8,%9}, {%0,%1,%2,%3};"
        : "+r"(c[0]), "+r"(c[1]), "+r"(c[2]), "+r"(c[3])
        : "r"(a[0]), "r"(a[1]), "r"(a[2]), "r"(a[3]), "r"(b0), "r"(b1));
}

// stage one input row: h/l s8 planes, 16 ci-groups x 130 halo'd cols
__device__ __forceinline__ void stage_row(uint32_t* sx, const float* xn,
                                          int row, int w0, int tid) {
    uint32_t* dst = sx + ((row + NSLOT) & (NSLOT - 1)) * SLOT;
    const bool rok = (unsigned)row < (unsigned)Hdim;
    const float* rp = xn + (size_t)row * Wdim;
    for (int i = tid; i < 16 * 130; i += NTHR) {
        int cig = i / 130;
        int p = i - cig * 130;
        int col = w0 - 1 + p;
        const bool cok = rok && ((unsigned)col < (unsigned)Wdim);
        uint32_t hw = 0, lw = 0;
#pragma unroll
        for (int j = 0; j < 4; j++) {
            float v = cok ? rp[(size_t)(cig * 4 + j) * HW + col] : 0.0f;
            int hq = __float2int_rn(16.0f * v);
            int lq = __float2int_rn(fmaf(2048.0f, v, -128.0f * (float)hq));
            hw |= (uint32_t)(hq & 0xff) << (8 * j);
            lw |= (uint32_t)(lq & 0xff) << (8 * j);
        }
        dst[cig * PXS + p] = hw;
        dst[PLANE + cig * PXS + p] = lw;
    }
}

// ---------------------------------------------------------------- conv
// grid (2, 56, 16): w0 = 0/96 (32px overlap writes identical values), 4-row h chunk, n.
// 256 threads = 8 warps: 4 M-warps (32px each) x 2 N-warps (32co each). 1 row/iter.
__global__ void __launch_bounds__(NTHR, 2)
conv_kernel(const float* __restrict__ x, const float* __restrict__ bias,
            float* __restrict__ out) {
    extern __shared__ char smem[];
    uint32_t* wsm = (uint32_t*)smem;
    uint32_t* sx = (uint32_t*)(smem + X_OFF);

    const int tid = threadIdx.x, lane = tid & 31, wid = tid >> 5;
    const int gr = lane >> 2, tc = lane & 3;
    const int wm = wid & 3, wn = wid >> 2;
    const int colb = wm * 32;
    const int w0 = blockIdx.x * 96;
    const int h0 = blockIdx.y * HC;
    const int n  = blockIdx.z;
    const float* xn = x + (size_t)n * C_IN * HW;

    // stage weights: g_tb8 (u32 view) -> smem [tap][cig stride 72][co]
    {
        const uint32_t* src = (const uint32_t*)g_tb8;
        for (int i = tid; i < 9 * 16 * 64; i += NTHR) {
            int tap = i >> 10;
            int rem = i & 1023;
            int cig = rem >> 6, co = rem & 63;
            wsm[tap * TAPW + cig * WCI32 + co] = src[i];
        }
    }

    // per-thread scale/bias for owned co pair
    float als[4][2], bis[4][2];
#pragma unroll
    for (int nt = 0; nt < 4; nt++) {
        int co = wn * 32 + nt * 8 + 2 * tc;
        als[nt][0] = g_alpha[co] * (1.0f / 2048.0f);
        als[nt][1] = g_alpha[co + 1] * (1.0f / 2048.0f);
        bis[nt][0] = bias[co];
        bis[nt][1] = bias[co + 1];
    }

    stage_row(sx, xn, h0 - 1, w0, tid);
    stage_row(sx, xn, h0,     w0, tid);
    stage_row(sx, xn, h0 + 1, w0, tid);
    stage_row(sx, xn, h0 + 2, w0, tid);

    for (int it = 0; it < HC; it++) {
        const int h = h0 + it;
        if (it > 0) stage_row(sx, xn, h + 2, w0, tid);
        __syncthreads();

        int acch[2][4][4], accl[2][4][4];
#pragma unroll
        for (int mt = 0; mt < 2; mt++)
#pragma unroll
            for (int nt = 0; nt < 4; nt++)
#pragma unroll
                for (int e = 0; e < 4; e++) { acch[mt][nt][e] = 0; accl[mt][nt][e] = 0; }

#pragma unroll 1
        for (int kh = 0; kh < 3; kh++) {
            const uint32_t* slotp = sx + ((h + kh - 1 + NSLOT) & (NSLOT - 1)) * SLOT;
#pragma unroll 1
            for (int kw = 0; kw < 3; kw++) {
                const uint32_t* ap_base = slotp + tc * PXS + colb + kw + gr;
                const uint32_t* bp = wsm + (kh * 3 + kw) * TAPW + tc * WCI32 + wn * 32 + gr;
#pragma unroll
                for (int ks = 0; ks < 2; ks++) {
                    const uint32_t* ap = ap_base + (8 * ks) * PXS;
                    const uint32_t* bq = bp + (8 * ks) * WCI32;
                    // B fragments (shared by h and l passes)
                    uint32_t B0[4], B1[4];
#pragma unroll
                    for (int nt = 0; nt < 4; nt++) {
                        B0[nt] = bq[nt * 8];
                        B1[nt] = bq[nt * 8 + 4 * WCI32];
                    }
                    uint32_t Ah[2][4], Al[2][4];
#pragma unroll
                    for (int mt = 0; mt < 2; mt++) {
                        const uint32_t* a = ap + mt * 16;
                        Ah[mt][0] = a[0];
                        Ah[mt][1] = a[8];
                        Ah[mt][2] = a[4 * PXS];
                        Ah[mt][3] = a[4 * PXS + 8];
                        const uint32_t* al_ = a + PLANE;
                        Al[mt][0] = al_[0];
                        Al[mt][1] = al_[8];
                        Al[mt][2] = al_[4 * PXS];
                        Al[mt][3] = al_[4 * PXS + 8];
                    }
#pragma unroll
                    for (int nt = 0; nt < 4; nt++) {
                        imma(acch[0][nt], Ah[0], B0[nt], B1[nt]);
                        imma(acch[1][nt], Ah[1], B0[nt], B1[nt]);
                        imma(accl[0][nt], Al[0], B0[nt], B1[nt]);
                        imma(accl[1][nt], Al[1], B0[nt], B1[nt]);
                    }
                }
            }
        }

        // epilogue: out = (128*acc_h + acc_l) * alpha/2048 + bias
#pragma unroll
        for (int mt = 0; mt < 2; mt++) {
#pragma unroll
            for (int nt = 0; nt < 4; nt++) {
                int co = wn * 32 + nt * 8 + 2 * tc;
                int wg = w0 + colb + mt * 16 + gr;
                float* p = out + ((size_t)(n * C_OUT + co)) * HW + (size_t)h * Wdim + wg;
                float v0 = (float)(acch[mt][nt][0] * 128 + accl[mt][nt][0]);
                float v1 = (float)(acch[mt][nt][1] * 128 + accl[mt][nt][1]);
                float v2 = (float)(acch[mt][nt][2] * 128 + accl[mt][nt][2]);
                float v3 = (float)(acch[mt][nt][3] * 128 + accl[mt][nt][3]);
                p[0]      = v0 * als[nt][0] + bis[nt][0];
                p[HW]     = v1 * als[nt][1] + bis[nt][1];
                p[8]      = v2 * als[nt][0] + bis[nt][0];
                p[HW + 8] = v3 * als[nt][1] + bis[nt][1];
            }
        }
        __syncthreads();
    }
}

extern "C" void kernel_launch(void* const* d_in, const int* in_sizes, int n_in,
                              void* d_out, int out_size) {
    const float* x      = (const float*)d_in[0];
    const float* weight = (const float*)d_in[1];
    const float* bias   = (const float*)d_in[2];
    float* out          = (float*)d_out;

    cudaFuncSetAttribute(conv_kernel, cudaFuncAttributeMaxDynamicSharedMemorySize,
                         SMEM_TOTAL);

    ternarize_kernel<<<C_OUT, 256>>>(weight);

    dim3 grid(2, Hdim / HC, 16);   // (2, 56, 16)
    conv_kernel<<<grid, NTHR, SMEM_TOTAL>>>(x, bias, out);
}

// round 7
// speedup vs baseline: 1.6207x; 1.6207x over previous
#include <cuda_runtime.h>
#include <cuda_fp16.h>
#include <cstdint>

#define C_IN   64
#define C_OUT  64
#define Hdim   224
#define Wdim   224
#define HW     (Hdim * Wdim)
#define HC     4
#define NTHR   256

// weight smem: [tap][cipair(stride 72 u32)][co 64]
#define WCP    72
#define TAPW   (32 * WCP)               // 2304 u32 per tap
#define WS_BYTES (9 * TAPW * 4)         // 82944
// fp16 x ring: 4 slots x [cipair 32 (stride 136 u32)][col 130]
#define PXS    136
#define SLOTU  (32 * PXS)               // 4352 u32
#define X_OFF  WS_BYTES
#define RING_BYTES (4 * SLOTU * 4)      // 69632
// raw f32 double buffer: interior [ci 64][128], halo [ci 64][2]
#define RAWI_OFF (X_OFF + RING_BYTES)                  // 152576
#define RAWI_SLOT 8192                                 // u32 per par
#define HALO_OFF (RAWI_OFF + 2 * RAWI_SLOT * 4)        // 218112
#define SMEM_TOTAL (HALO_OFF + 2 * 128 * 4)            // 219136

// ternary weights as packed fp16 pairs: u32 index (tap*32 + ci/2)*64 + co,
// halves: low = ci even, high = ci odd
__device__ unsigned short g_twp[9 * 32 * C_OUT * 2];
__device__ float g_alpha[C_OUT];

// ---------------------------------------------------------------- ternarize
__global__ void ternarize_kernel(const float* __restrict__ weight) {
    __shared__ float red[256], red2[256];
    __shared__ float s_delta, s_alpha;
    const int co = blockIdx.x, tid = threadIdx.x;
    const float* w = weight + co * 576;

    float v0 = (tid < 576) ? w[tid] : 0.0f;
    float v1 = (tid + 256 < 576) ? w[tid + 256] : 0.0f;
    float v2 = (tid + 512 < 576) ? w[tid + 512] : 0.0f;
    float a0 = fabsf(v0), a1 = fabsf(v1), a2 = fabsf(v2);

    red[tid] = a0 + a1 + a2;
    __syncthreads();
    for (int s = 128; s > 0; s >>= 1) { if (tid < s) red[tid] += red[tid + s]; __syncthreads(); }
    if (tid == 0) s_delta = (float)(0.7 / 576.0) * red[0];
    __syncthreads();
    const float delta = s_delta;

    float m0 = (a0 > delta) ? 1.f : 0.f, m1 = (a1 > delta) ? 1.f : 0.f, m2 = (a2 > delta) ? 1.f : 0.f;
    red[tid] = m0 * a0 + m1 * a1 + m2 * a2;
    red2[tid] = m0 + m1 + m2;
    __syncthreads();
    for (int s = 128; s > 0; s >>= 1) {
        if (tid < s) { red[tid] += red[tid + s]; red2[tid] += red2[tid + s]; }
        __syncthreads();
    }
    if (tid == 0) {
        float cnt = red2[0]; if (cnt < 0.5f) cnt = 1.0f;
        s_alpha = fmaxf(red[0] / cnt, 1e-4f);
        g_alpha[co] = s_alpha;
    }
    __syncthreads();

#pragma unroll
    for (int q = 0; q < 3; q++) {
        int f = tid + q * 256;
        if (f < 576) {
            float v = (q == 0) ? v0 : (q == 1) ? v1 : v2;
            float t = (v > delta) ? 1.0f : ((v < -delta) ? -1.0f : 0.0f);
            int ci = f / 9, tap = f % 9;     // weight layout [co][ci][kh][kw]
            g_twp[((tap * 32 + (ci >> 1)) * C_OUT + co) * 2 + (ci & 1)] =
                __half_as_ushort(__float2half_rn(t));
        }
    }
}

// ---------------------------------------------------------------- helpers
__device__ __forceinline__ void mma_h(float* c, const uint32_t* a, uint32_t b0, uint32_t b1) {
    asm volatile(
        "mma.sync.aligned.m16n8k16.row.col.f32.f16.f16.f32 "
        "{%0,%1,%2,%3}, {%4,%5,%6,%7}, {%8,%9}, {%0,%1,%2,%3};"
        : "+f"(c[0]), "+f"(c[1]), "+f"(c[2]), "+f"(c[3])
        : "r"(a[0]), "r"(a[1]), "r"(a[2]), "r"(a[3]), "r"(b0), "r"(b1));
}
__device__ __forceinline__ uint32_t smem_u32(const void* p) {
    uint32_t a;
    asm("{ .reg .u64 t; cvta.to.shared.u64 t, %1; cvt.u32.u64 %0, t; }" : "=r"(a) : "l"(p));
    return a;
}
__device__ __forceinline__ void cp16(uint32_t dst, const void* src, int sz) {
    asm volatile("cp.async.cg.shared.global [%0], [%1], 16, %2;"
                 :: "r"(dst), "l"(src), "r"(sz) : "memory");
}
__device__ __forceinline__ void cp4(uint32_t dst, const void* src, int sz) {
    asm volatile("cp.async.ca.shared.global [%0], [%1], 4, %2;"
                 :: "r"(dst), "l"(src), "r"(sz) : "memory");
}
__device__ __forceinline__ uint32_t packh2(float lo, float hi) {
    return (uint32_t)__half_as_ushort(__float2half_rn(lo)) |
           ((uint32_t)__half_as_ushort(__float2half_rn(hi)) << 16);
}

// direct (blocking) stage of one row into the fp16 ring — prologue only
__device__ __forceinline__ void stage_direct(uint32_t* sx, const float* xn,
                                             int row, int w0, int tid) {
    uint32_t* dst = sx + ((row + 4) & 3) * SLOTU;
    const bool rok = (unsigned)row < (unsigned)Hdim;
    const float* rp = xn + (size_t)row * Wdim;
    for (int j = tid; j < 32 * 130; j += NTHR) {
        int c = j / 130;
        int p = j - c * 130;
        int col = w0 - 1 + p;
        const bool cok = rok && ((unsigned)col < (unsigned)Wdim);
        float v0 = cok ? rp[(size_t)(2 * c) * HW + col] : 0.0f;
        float v1 = cok ? rp[(size_t)(2 * c + 1) * HW + col] : 0.0f;
        dst[c * PXS + p] = packh2(v0, v1);
    }
}

// async stage of raw f32 row into raw[par]
// interior: 64 ci x 128 cols f32 = 2048 16B chunks = 8 per thread
__device__ __forceinline__ void cp_stage(char* smem, const float* xn,
                                         int row, int par, int w0, int tid) {
    const bool rok = (unsigned)row < (unsigned)Hdim;
    const int srow = rok ? row : 0;
    const int sz16 = rok ? 16 : 0;
    const uint32_t rawi_a = smem_u32(smem + RAWI_OFF) + par * (RAWI_SLOT * 4);
    const uint32_t rawh_a = smem_u32(smem + HALO_OFF) + par * 512;
#pragma unroll
    for (int k = 0; k < 8; k++) {
        int idx = tid + k * NTHR;          // 0..2047
        int ci = idx >> 5;                 // 0..63
        int cpos = (idx & 31) << 2;        // 0..124, 4 f32 per chunk
        cp16(rawi_a + (uint32_t)(ci * 128 + cpos) * 4,
             xn + (size_t)ci * HW + (size_t)srow * Wdim + w0 + cpos, sz16);
    }
    if (tid < 128) {
        int ci = tid >> 1, side = tid & 1;
        int col = w0 - 1 + side * 129;
        const bool ok = rok && ((unsigned)col < (unsigned)Wdim);
        cp4(rawh_a + (uint32_t)tid * 4,
            xn + (size_t)ci * HW + (size_t)srow * Wdim + (ok ? col : 0), ok ? 4 : 0);
    }
    asm volatile("cp.async.commit_group;" ::: "memory");
}

// convert raw[par] -> fp16 ring slot for `row`
__device__ __forceinline__ void convert_row(char* smem, uint32_t* sx,
                                            int row, int par, int tid) {
    const float* rawi = (const float*)(smem + RAWI_OFF) + par * RAWI_SLOT;
    const float* rawh = (const float*)(smem + HALO_OFF) + par * 128;
    uint32_t* dst = sx + ((row + 4) & 3) * SLOTU;
    for (int j = tid; j < 32 * 130; j += NTHR) {
        int c = j / 130;
        int p = j - c * 130;
        float v0, v1;
        if (p == 0)        { v0 = rawh[(2 * c) * 2];     v1 = rawh[(2 * c + 1) * 2]; }
        else if (p == 129) { v0 = rawh[(2 * c) * 2 + 1]; v1 = rawh[(2 * c + 1) * 2 + 1]; }
        else               { v0 = rawi[(2 * c) * 128 + p - 1];
                             v1 = rawi[(2 * c + 1) * 128 + p - 1]; }
        dst[c * PXS + p] = packh2(v0, v1);
    }
}

// ---------------------------------------------------------------- conv
// grid (2, 56, 16). 256 thr = 8 warps: 4 M-warps (32 px) x 2 N-warps (32 co).
__global__ void __launch_bounds__(NTHR, 1)
conv_kernel(const float* __restrict__ x, const float* __restrict__ bias,
            float* __restrict__ out) {
    extern __shared__ char smem[];
    uint32_t* wsm = (uint32_t*)smem;
    uint32_t* sx = (uint32_t*)(smem + X_OFF);

    const int tid = threadIdx.x, lane = tid & 31, wid = tid >> 5;
    const int gr = lane >> 2, tc = lane & 3;
    const int wm = wid & 3, wn = wid >> 2;
    const int colb = wm * 32;
    const int w0 = blockIdx.x * 96;
    const int h0 = blockIdx.y * HC;
    const int n  = blockIdx.z;
    const float* xn = x + (size_t)n * C_IN * HW;

    // stage weights: g_twp (u32 view, [tap][cipair][co]) -> smem strided
    {
        const uint32_t* src = (const uint32_t*)g_twp;
        for (int i = tid; i < 9 * 32 * 64; i += NTHR) {
            int tap = i >> 11;
            int rem = i & 2047;
            int cp = rem >> 6, co = rem & 63;
            wsm[tap * TAPW + cp * WCP + co] = src[i];
        }
    }

    float als[4][2], bis[4][2];
#pragma unroll
    for (int nt = 0; nt < 4; nt++) {
        int co = wn * 32 + nt * 8 + 2 * tc;
        als[nt][0] = g_alpha[co];     als[nt][1] = g_alpha[co + 1];
        bis[nt][0] = bias[co];        bis[nt][1] = bias[co + 1];
    }

    stage_direct(sx, xn, h0 - 1, w0, tid);
    stage_direct(sx, xn, h0,     w0, tid);
    stage_direct(sx, xn, h0 + 1, w0, tid);
    cp_stage(smem, xn, h0 + 2, 0, w0, tid);
    int par = 0;

    for (int it = 0; it < HC; it++) {
        const int h = h0 + it;
        if (it > 0) {
            asm volatile("cp.async.wait_group 0;" ::: "memory");
            __syncthreads();                       // raw[par] visible to all
            convert_row(smem, sx, h + 1, par, tid);
            if (it < 3) cp_stage(smem, xn, h + 2, par ^ 1, w0, tid);
            par ^= 1;
        }
        __syncthreads();                           // ring slots ready

        float acc[2][4][4];
#pragma unroll
        for (int mt = 0; mt < 2; mt++)
#pragma unroll
            for (int nt = 0; nt < 4; nt++)
#pragma unroll
                for (int e = 0; e < 4; e++) acc[mt][nt][e] = 0.0f;

#pragma unroll 1
        for (int kh = 0; kh < 3; kh++) {
            const uint32_t* slotp = sx + ((h + kh - 1 + 4) & 3) * SLOTU;
#pragma unroll 1
            for (int kw = 0; kw < 3; kw++) {
                const uint32_t* ap_base = slotp + tc * PXS + colb + kw + gr;
                const uint32_t* bp = wsm + (kh * 3 + kw) * TAPW + tc * WCP + wn * 32 + gr;
#pragma unroll
                for (int ks = 0; ks < 4; ks++) {
                    const uint32_t* ap = ap_base + (8 * ks) * PXS;
                    const uint32_t* bq = bp + (8 * ks) * WCP;
                    uint32_t B0[4], B1[4];
#pragma unroll
                    for (int nt = 0; nt < 4; nt++) {
                        B0[nt] = bq[nt * 8];
                        B1[nt] = bq[nt * 8 + 4 * WCP];
                    }
                    uint32_t A[2][4];
#pragma unroll
                    for (int mt = 0; mt < 2; mt++) {
                        const uint32_t* a = ap + mt * 16;
                        A[mt][0] = a[0];
                        A[mt][1] = a[8];
                        A[mt][2] = a[4 * PXS];
                        A[mt][3] = a[4 * PXS + 8];
                    }
#pragma unroll
                    for (int nt = 0; nt < 4; nt++) {
                        mma_h(acc[0][nt], A[0], B0[nt], B1[nt]);
                        mma_h(acc[1][nt], A[1], B0[nt], B1[nt]);
                    }
                }
            }
        }

        // epilogue
#pragma unroll
        for (int mt = 0; mt < 2; mt++) {
#pragma unroll
            for (int nt = 0; nt < 4; nt++) {
                int co = wn * 32 + nt * 8 + 2 * tc;
                int wg = w0 + colb + mt * 16 + gr;
                float* p = out + ((size_t)(n * C_OUT + co)) * HW + (size_t)h * Wdim + wg;
                p[0]      = acc[mt][nt][0] * als[nt][0] + bis[nt][0];
                p[HW]     = acc[mt][nt][1] * als[nt][1] + bis[nt][1];
                p[8]      = acc[mt][nt][2] * als[nt][0] + bis[nt][0];
                p[HW + 8] = acc[mt][nt][3] * als[nt][1] + bis[nt][1];
            }
        }
    }
}

extern "C" void kernel_launch(void* const* d_in, const int* in_sizes, int n_in,
                              void* d_out, int out_size) {
    const float* x      = (const float*)d_in[0];
    const float* weight = (const float*)d_in[1];
    const float* bias   = (const float*)d_in[2];
    float* out          = (float*)d_out;

    cudaFuncSetAttribute(conv_kernel, cudaFuncAttributeMaxDynamicSharedMemorySize,
                         SMEM_TOTAL);

    ternarize_kernel<<<C_OUT, 256>>>(weight);

    dim3 grid(2, Hdim / HC, 16);   // (2, 56, 16)
    conv_kernel<<<grid, NTHR, SMEM_TOTAL>>>(x, bias, out);
}

// round 9
// speedup vs baseline: 3.9013x; 2.4071x over previous
#include <cuda_runtime.h>
#include <cuda_fp16.h>
#include <cstdint>

#define C_IN   64
#define C_OUT  64
#define Hdim   224
#define Wdim   224
#define HW     (Hdim * Wdim)
#define HC     8
#define NTHR   256

// weight smem: [tap][cipair(stride 72 u32)][co 64]
#define WCP    72
#define TAPW   (32 * WCP)               // 2304 u32 per tap
#define WS_U32 (9 * TAPW)               // 20736 u32
#define X_OFF  (WS_U32 * 4)             // 82944 B
// fp16 x ring: 8 slots x [cipair 32 (stride 136 u32)]; halos at j=3/132, interior 4..131
#define PXS    136
#define SLOTU  (32 * PXS)               // 4352 u32
#define NSLOT  8
#define SMEM_TOTAL (X_OFF + NSLOT * SLOTU * 4)   // 222208 B

// packed fp16 ci-pairs of x: [n][cipair 32][h][w], u32 = (half ci_even | half ci_odd << 16)
__device__ __align__(16) uint32_t g_xh[16 * 32 * HW];
// ternary weights as packed fp16 pairs: u32 index (tap*32 + ci/2)*64 + co
__device__ __align__(16) unsigned short g_twp[9 * 32 * C_OUT * 2];
__device__ float g_alpha[C_OUT];

// ---------------------------------------------------------------- helpers
__device__ __forceinline__ uint32_t smem_u32(const void* p) {
    uint32_t a;
    asm("{ .reg .u64 t; cvta.to.shared.u64 t, %1; cvt.u32.u64 %0, t; }" : "=r"(a) : "l"(p));
    return a;
}
__device__ __forceinline__ void cp16(uint32_t dst, const void* src, int sz) {
    asm volatile("cp.async.cg.shared.global [%0], [%1], 16, %2;"
                 :: "r"(dst), "l"(src), "r"(sz) : "memory");
}
__device__ __forceinline__ void cp4(uint32_t dst, const void* src, int sz) {
    asm volatile("cp.async.ca.shared.global [%0], [%1], 4, %2;"
                 :: "r"(dst), "l"(src), "r"(sz) : "memory");
}
__device__ __forceinline__ uint32_t packh2(float lo, float hi) {
    return (uint32_t)__half_as_ushort(__float2half_rn(lo)) |
           ((uint32_t)__half_as_ushort(__float2half_rn(hi)) << 16);
}
__device__ __forceinline__ void mma_h(float* c, const uint32_t* a, uint32_t b0, uint32_t b1) {
    asm volatile(
        "mma.sync.aligned.m16n8k16.row.col.f32.f16.f16.f32 "
        "{%0,%1,%2,%3}, {%4,%5,%6,%7}, {%8,%9}, {%0,%1,%2,%3};"
        : "+f"(c[0]), "+f"(c[1]), "+f"(c[2]), "+f"(c[3])
        : "r"(a[0]), "r"(a[1]), "r"(a[2]), "r"(a[3]), "r"(b0), "r"(b1));
}

// ---------------------------------------------------------------- prepass: f32 -> packed fp16 pairs
__global__ void __launch_bounds__(256) prepass_kernel(const float* __restrict__ x) {
    int idx = blockIdx.x * 256 + threadIdx.x;           // uint4 index
    int u = idx * 4;                                    // u32 index
    int n = u / (32 * HW);
    int r = u - n * (32 * HW);
    int c = r / HW;
    int p = r - c * HW;
    const float4 a = *(const float4*)(x + ((size_t)(n * 64 + 2 * c) * HW + p));
    const float4 b = *(const float4*)(x + ((size_t)(n * 64 + 2 * c + 1) * HW + p));
    uint4 o;
    o.x = packh2(a.x, b.x);
    o.y = packh2(a.y, b.y);
    o.z = packh2(a.z, b.z);
    o.w = packh2(a.w, b.w);
    *(uint4*)(g_xh + u) = o;
}

// ---------------------------------------------------------------- ternarize
__global__ void ternarize_kernel(const float* __restrict__ weight) {
    __shared__ float red[256], red2[256];
    __shared__ float s_delta, s_alpha;
    const int co = blockIdx.x, tid = threadIdx.x;
    const float* w = weight + co * 576;

    float v0 = (tid < 576) ? w[tid] : 0.0f;
    float v1 = (tid + 256 < 576) ? w[tid + 256] : 0.0f;
    float v2 = (tid + 512 < 576) ? w[tid + 512] : 0.0f;
    float a0 = fabsf(v0), a1 = fabsf(v1), a2 = fabsf(v2);

    red[tid] = a0 + a1 + a2;
    __syncthreads();
    for (int s = 128; s > 0; s >>= 1) { if (tid < s) red[tid] += red[tid + s]; __syncthreads(); }
    if (tid == 0) s_delta = (float)(0.7 / 576.0) * red[0];
    __syncthreads();
    const float delta = s_delta;

    float m0 = (a0 > delta) ? 1.f : 0.f, m1 = (a1 > delta) ? 1.f : 0.f, m2 = (a2 > delta) ? 1.f : 0.f;
    red[tid] = m0 * a0 + m1 * a1 + m2 * a2;
    red2[tid] = m0 + m1 + m2;
    __syncthreads();
    for (int s = 128; s > 0; s >>= 1) {
        if (tid < s) { red[tid] += red[tid + s]; red2[tid] += red2[tid + s]; }
        __syncthreads();
    }
    if (tid == 0) {
        float cnt = red2[0]; if (cnt < 0.5f) cnt = 1.0f;
        s_alpha = fmaxf(red[0] / cnt, 1e-4f);
        g_alpha[co] = s_alpha;
    }
    __syncthreads();

#pragma unroll
    for (int q = 0; q < 3; q++) {
        int f = tid + q * 256;
        if (f < 576) {
            float v = (q == 0) ? v0 : (q == 1) ? v1 : v2;
            float t = (v > delta) ? 1.0f : ((v < -delta) ? -1.0f : 0.0f);
            int ci = f / 9, tap = f % 9;     // weight layout [co][ci][kh][kw]
            g_twp[((tap * 32 + (ci >> 1)) * C_OUT + co) * 2 + (ci & 1)] =
                __half_as_ushort(__float2half_rn(t));
        }
    }
}

// ---------------------------------------------------------------- row staging (cp.async, commits one group)
__device__ __forceinline__ void cp_stage(uint32_t sxa, int n, int row, int w0, int tid) {
    const bool rok = (unsigned)row < (unsigned)Hdim;
    const int srow = rok ? row : 0;
    const int sz16 = rok ? 16 : 0;
    const uint32_t slot_b = sxa + (uint32_t)(((row + NSLOT) & (NSLOT - 1)) * SLOTU) * 4;
    const uint32_t* xb = g_xh + (size_t)n * 32 * HW + (size_t)srow * Wdim;
#pragma unroll
    for (int k = 0; k < 4; k++) {
        int idx = tid + k * NTHR;            // 0..1023
        int c = idx >> 5;                    // cipair 0..31
        int q = (idx & 31) << 2;             // 0..124
        cp16(slot_b + (uint32_t)(c * PXS + 4 + q) * 4,
             xb + (size_t)c * HW + w0 + q, sz16);
    }
    if (tid < 64) {
        int c = tid >> 1, side = tid & 1;
        int col = w0 - 1 + side * 129;
        const bool ok = rok && ((unsigned)col < (unsigned)Wdim);
        cp4(slot_b + (uint32_t)(c * PXS + 3 + side * 129) * 4,
            xb + (size_t)c * HW + (ok ? col : 0), ok ? 4 : 0);
    }
    asm volatile("cp.async.commit_group;" ::: "memory");
}

// ---------------------------------------------------------------- conv
// grid (2, 28, 16). 256 thr = 8 warps: 4 M-warps (32 px) x 2 N-warps (32 co).
// bx=1 (w0=96) overlaps cols 96..127 with bx=0; its wm==0 warps skip MMA+store.
__global__ void __launch_bounds__(NTHR, 1)
conv_kernel(const float* __restrict__ bias, float* __restrict__ out) {
    extern __shared__ char smem[];
    uint32_t* wsm = (uint32_t*)smem;
    uint32_t* sx = (uint32_t*)(smem + X_OFF);
    const uint32_t wsa = smem_u32(smem);
    const uint32_t sxa = smem_u32(smem + X_OFF);

    const int tid = threadIdx.x, lane = tid & 31, wid = tid >> 5;
    const int gr = lane >> 2, tc = lane & 3;
    const int wm = wid & 3, wn = wid >> 2;
    const int colb = wm * 32;
    const int w0 = blockIdx.x * 96;
    const int h0 = blockIdx.y * HC;
    const int n  = blockIdx.z;
    const bool do_mma = !(blockIdx.x == 1 && wm == 0);

    // group 1: weights -> smem [tap][cipair stride 72][co], via cp.async
    // 9 taps x 32 cipairs x 16 chunks(16B) = 4608 chunks, 18 per thread
    {
        const uint32_t* src = (const uint32_t*)g_twp;
#pragma unroll
        for (int k = 0; k < 18; k++) {
            int chunk = tid + k * NTHR;          // 0..4607
            int tap = chunk >> 9;                // /512
            int rem = chunk & 511;
            int cp = rem >> 4;                   // cipair 0..31
            int kk = rem & 15;                   // 16B chunk within 64 u32
            cp16(wsa + (uint32_t)(tap * TAPW + cp * WCP + kk * 4) * 4,
                 src + (size_t)(tap * 32 + cp) * 64 + kk * 4, 16);
        }
        asm volatile("cp.async.commit_group;" ::: "memory");
    }

    float als[4][2], bis[4][2];
#pragma unroll
    for (int nt = 0; nt < 4; nt++) {
        int co = wn * 32 + nt * 8 + 2 * tc;
        als[nt][0] = g_alpha[co];     als[nt][1] = g_alpha[co + 1];
        bis[nt][0] = bias[co];        bis[nt][1] = bias[co + 1];
    }

    cp_stage(sxa, n, h0 - 1, w0, tid);
    cp_stage(sxa, n, h0,     w0, tid);
    cp_stage(sxa, n, h0 + 1, w0, tid);

    for (int it = 0; it < HC; it++) {
        const int h = h0 + it;
        if (it < HC - 1) {
            cp_stage(sxa, n, h + 2, w0, tid);
            asm volatile("cp.async.wait_group 1;" ::: "memory");
        } else {
            asm volatile("cp.async.wait_group 0;" ::: "memory");
        }
        __syncthreads();     // rows h-1..h+1 (and weights) visible

        if (do_mma) {
            float acc[2][4][4];
#pragma unroll
            for (int mt = 0; mt < 2; mt++)
#pragma unroll
                for (int nt = 0; nt < 4; nt++)
#pragma unroll
                    for (int e = 0; e < 4; e++) acc[mt][nt][e] = 0.0f;

#pragma unroll 1
            for (int kh = 0; kh < 3; kh++) {
                const uint32_t* slotp = sx + ((h + kh - 1 + NSLOT) & (NSLOT - 1)) * SLOTU;
#pragma unroll 1
                for (int kw = 0; kw < 3; kw++) {
                    const uint32_t* ap_base = slotp + tc * PXS + 3 + colb + kw + gr;
                    const uint32_t* bp = wsm + (kh * 3 + kw) * TAPW + tc * WCP + wn * 32 + gr;
#pragma unroll
                    for (int ks = 0; ks < 4; ks++) {
                        const uint32_t* ap = ap_base + (8 * ks) * PXS;
                        const uint32_t* bq = bp + (8 * ks) * WCP;
                        uint32_t B0[4], B1[4];
#pragma unroll
                        for (int nt = 0; nt < 4; nt++) {
                            B0[nt] = bq[nt * 8];
                            B1[nt] = bq[nt * 8 + 4 * WCP];
                        }
                        uint32_t A[2][4];
#pragma unroll
                        for (int mt = 0; mt < 2; mt++) {
                            const uint32_t* a = ap + mt * 16;
                            A[mt][0] = a[0];
                            A[mt][1] = a[8];
                            A[mt][2] = a[4 * PXS];
                            A[mt][3] = a[4 * PXS + 8];
                        }
#pragma unroll
                        for (int nt = 0; nt < 4; nt++) {
                            mma_h(acc[0][nt], A[0], B0[nt], B1[nt]);
                            mma_h(acc[1][nt], A[1], B0[nt], B1[nt]);
                        }
                    }
                }
            }

            // epilogue
#pragma unroll
            for (int mt = 0; mt < 2; mt++) {
#pragma unroll
                for (int nt = 0; nt < 4; nt++) {
                    int co = wn * 32 + nt * 8 + 2 * tc;
                    int wg = w0 + colb + mt * 16 + gr;
                    float* p = out + ((size_t)(n * C_OUT + co)) * HW + (size_t)h * Wdim + wg;
                    p[0]      = acc[mt][nt][0] * als[nt][0] + bis[nt][0];
                    p[HW]     = acc[mt][nt][1] * als[nt][1] + bis[nt][1];
                    p[8]      = acc[mt][nt][2] * als[nt][0] + bis[nt][0];
                    p[HW + 8] = acc[mt][nt][3] * als[nt][1] + bis[nt][1];
                }
            }
        }
        __syncthreads();     // all reads of slot (h-1) done before it is re-staged
    }
}

extern "C" void kernel_launch(void* const* d_in, const int* in_sizes, int n_in,
                              void* d_out, int out_size) {
    const float* x      = (const float*)d_in[0];
    const float* weight = (const float*)d_in[1];
    const float* bias   = (const float*)d_in[2];
    float* out          = (float*)d_out;

    cudaFuncSetAttribute(conv_kernel, cudaFuncAttributeMaxDynamicSharedMemorySize,
                         SMEM_TOTAL);

    prepass_kernel<<<16 * 32 * HW / 4 / 256, 256>>>(x);
    ternarize_kernel<<<C_OUT, 256>>>(weight);

    dim3 grid(2, Hdim / HC, 16);   // (2, 28, 16)
    conv_kernel<<<grid, NTHR, SMEM_TOTAL>>>(bias, out);
}

// round 10
// speedup vs baseline: 4.3225x; 1.1080x over previous
#include <cuda_runtime.h>
#include <cuda_fp16.h>
#include <cstdint>

#define C_IN   64
#define C_OUT  64
#define Hdim   224
#define Wdim   224
#define HW     (Hdim * Wdim)
#define NTHR   256

// B weight smem: u64 units, index = ((tap*4+ks)*8 + wn*4 + nt)*32 + gr*4 + tc
#define WS_BYTES (9 * 4 * 8 * 32 * 8)   // 73728
#define X_OFF    WS_BYTES
// fp16 x ring: 8 slots x [cipair 32 (stride 136 u32)]; halos at j=3/132, interior 4..131
#define PXS    136
#define SLOTU  (32 * PXS)               // 4352 u32
#define NSLOT  8
#define SMEM_TOTAL (X_OFF + NSLOT * SLOTU * 4)   // 212992 B

// packed fp16 ci-pairs of x: [n][cipair 32][h][w]
__device__ __align__(16) uint32_t g_xh[16 * 32 * HW];
// ternary weights, LDS.64-friendly fragment layout (see ternarize)
__device__ __align__(16) unsigned short g_twB[9 * 4 * 8 * 32 * 4];
__device__ float g_alpha[C_OUT];

// ---------------------------------------------------------------- helpers
__device__ __forceinline__ uint32_t smem_u32(const void* p) {
    uint32_t a;
    asm("{ .reg .u64 t; cvta.to.shared.u64 t, %1; cvt.u32.u64 %0, t; }" : "=r"(a) : "l"(p));
    return a;
}
__device__ __forceinline__ void cp16(uint32_t dst, const void* src, int sz) {
    asm volatile("cp.async.cg.shared.global [%0], [%1], 16, %2;"
                 :: "r"(dst), "l"(src), "r"(sz) : "memory");
}
__device__ __forceinline__ void cp4(uint32_t dst, const void* src, int sz) {
    asm volatile("cp.async.ca.shared.global [%0], [%1], 4, %2;"
                 :: "r"(dst), "l"(src), "r"(sz) : "memory");
}
__device__ __forceinline__ uint32_t packh2(float lo, float hi) {
    return (uint32_t)__half_as_ushort(__float2half_rn(lo)) |
           ((uint32_t)__half_as_ushort(__float2half_rn(hi)) << 16);
}
__device__ __forceinline__ void mma_h(float* c, const uint32_t* a, uint32_t b0, uint32_t b1) {
    asm volatile(
        "mma.sync.aligned.m16n8k16.row.col.f32.f16.f16.f32 "
        "{%0,%1,%2,%3}, {%4,%5,%6,%7}, {%8,%9}, {%0,%1,%2,%3};"
        : "+f"(c[0]), "+f"(c[1]), "+f"(c[2]), "+f"(c[3])
        : "r"(a[0]), "r"(a[1]), "r"(a[2]), "r"(a[3]), "r"(b0), "r"(b1));
}

// ---------------------------------------------------------------- prepass: f32 -> packed fp16 pairs
__global__ void __launch_bounds__(256) prepass_kernel(const float* __restrict__ x) {
    int idx = blockIdx.x * 256 + threadIdx.x;
    int u = idx * 4;
    int n = u / (32 * HW);
    int r = u - n * (32 * HW);
    int c = r / HW;
    int p = r - c * HW;
    const float4 a = *(const float4*)(x + ((size_t)(n * 64 + 2 * c) * HW + p));
    const float4 b = *(const float4*)(x + ((size_t)(n * 64 + 2 * c + 1) * HW + p));
    uint4 o;
    o.x = packh2(a.x, b.x);
    o.y = packh2(a.y, b.y);
    o.z = packh2(a.z, b.z);
    o.w = packh2(a.w, b.w);
    *(uint4*)(g_xh + u) = o;
}

// ---------------------------------------------------------------- ternarize
__global__ void ternarize_kernel(const float* __restrict__ weight) {
    __shared__ float red[256], red2[256];
    __shared__ float s_delta, s_alpha;
    const int co = blockIdx.x, tid = threadIdx.x;
    const float* w = weight + co * 576;

    float v0 = (tid < 576) ? w[tid] : 0.0f;
    float v1 = (tid + 256 < 576) ? w[tid + 256] : 0.0f;
    float v2 = (tid + 512 < 576) ? w[tid + 512] : 0.0f;
    float a0 = fabsf(v0), a1 = fabsf(v1), a2 = fabsf(v2);

    red[tid] = a0 + a1 + a2;
    __syncthreads();
    for (int s = 128; s > 0; s >>= 1) { if (tid < s) red[tid] += red[tid + s]; __syncthreads(); }
    if (tid == 0) s_delta = (float)(0.7 / 576.0) * red[0];
    __syncthreads();
    const float delta = s_delta;

    float m0 = (a0 > delta) ? 1.f : 0.f, m1 = (a1 > delta) ? 1.f : 0.f, m2 = (a2 > delta) ? 1.f : 0.f;
    red[tid] = m0 * a0 + m1 * a1 + m2 * a2;
    red2[tid] = m0 + m1 + m2;
    __syncthreads();
    for (int s = 128; s > 0; s >>= 1) {
        if (tid < s) { red[tid] += red[tid + s]; red2[tid] += red2[tid + s]; }
        __syncthreads();
    }
    if (tid == 0) {
        float cnt = red2[0]; if (cnt < 0.5f) cnt = 1.0f;
        s_alpha = fmaxf(red[0] / cnt, 1e-4f);
        g_alpha[co] = s_alpha;
    }
    __syncthreads();

    const int wn = co >> 5, nt = (co >> 3) & 3, grb = co & 7;
#pragma unroll
    for (int q = 0; q < 3; q++) {
        int f = tid + q * 256;
        if (f < 576) {
            float v = (q == 0) ? v0 : (q == 1) ? v1 : v2;
            float t = (v > delta) ? 1.0f : ((v < -delta) ? -1.0f : 0.0f);
            int ci = f / 9, tap = f % 9;     // weight layout [co][ci][kh][kw]
            int ks = ci >> 4, r = ci & 15;
            int word = r >> 3, rr = r & 7;
            int tcb = rr >> 1, e = rr & 1;
            int u64idx = (((tap * 4 + ks) * 8 + wn * 4 + nt) * 32) + grb * 4 + tcb;
            g_twB[u64idx * 4 + word * 2 + e] = __half_as_ushort(__float2half_rn(t));
        }
    }
}

// ---------------------------------------------------------------- row staging (cp.async, commits one group)
__device__ __forceinline__ void cp_stage(uint32_t sxa, int n, int row, int w0, int tid) {
    const bool rok = (unsigned)row < (unsigned)Hdim;
    const int srow = rok ? row : 0;
    const int sz16 = rok ? 16 : 0;
    const uint32_t slot_b = sxa + (uint32_t)(((row + NSLOT) & (NSLOT - 1)) * SLOTU) * 4;
    const uint32_t* xb = g_xh + (size_t)n * 32 * HW + (size_t)srow * Wdim;
#pragma unroll
    for (int k = 0; k < 4; k++) {
        int idx = tid + k * NTHR;            // 0..1023
        int c = idx >> 5;                    // cipair 0..31
        int q = (idx & 31) << 2;             // 0..124
        cp16(slot_b + (uint32_t)(c * PXS + 4 + q) * 4,
             xb + (size_t)c * HW + w0 + q, sz16);
    }
    if (tid < 64) {
        int c = tid >> 1, side = tid & 1;
        int col = w0 - 1 + side * 129;
        const bool ok = rok && ((unsigned)col < (unsigned)Wdim);
        cp4(slot_b + (uint32_t)(c * PXS + 3 + side * 129) * 4,
            xb + (size_t)c * HW + (ok ? col : 0), ok ? 4 : 0);
    }
    asm volatile("cp.async.commit_group;" ::: "memory");
}

// ---------------------------------------------------------------- conv
// grid (2, 28, 16). 256 thr = 8 warps: 4 M-warps (32 px) x 2 N-warps (32 co).
// Each iteration computes 2 output rows (4 iters = 8 rows per CTA).
// bx=1 (w0=96) overlaps cols 96..127 with bx=0; its wm==0 warps skip MMA+store.
__global__ void __launch_bounds__(NTHR, 1)
conv_kernel(const float* __restrict__ bias, float* __restrict__ out) {
    extern __shared__ char smem[];
    const uint2* B64 = (const uint2*)smem;
    uint32_t* sx = (uint32_t*)(smem + X_OFF);
    const uint32_t wsa = smem_u32(smem);
    const uint32_t sxa = smem_u32(smem + X_OFF);

    const int tid = threadIdx.x, lane = tid & 31, wid = tid >> 5;
    const int gr = lane >> 2, tc = lane & 3;
    const int wm = wid & 3, wn = wid >> 2;
    const int colb = wm * 32;
    const int w0 = blockIdx.x * 96;
    const int h0 = blockIdx.y * 8;
    const int n  = blockIdx.z;
    const bool do_mma = !(blockIdx.x == 1 && wm == 0);

    // weights -> smem, straight copy (layout prebuilt in ternarize): 4608 chunks
    {
#pragma unroll
        for (int k = 0; k < 18; k++) {
            int chunk = tid + k * NTHR;
            cp16(wsa + (uint32_t)chunk * 16, (const char*)g_twB + (size_t)chunk * 16, 16);
        }
        asm volatile("cp.async.commit_group;" ::: "memory");
    }

    float als[4][2], bis[4][2];
#pragma unroll
    for (int nt = 0; nt < 4; nt++) {
        int co = wn * 32 + nt * 8 + 2 * tc;
        als[nt][0] = g_alpha[co];     als[nt][1] = g_alpha[co + 1];
        bis[nt][0] = bias[co];        bis[nt][1] = bias[co + 1];
    }

    cp_stage(sxa, n, h0 - 1, w0, tid);
    cp_stage(sxa, n, h0,     w0, tid);
    cp_stage(sxa, n, h0 + 1, w0, tid);
    cp_stage(sxa, n, h0 + 2, w0, tid);

    for (int it = 0; it < 4; it++) {
        const int h = h0 + 2 * it;
        if (it < 3) {
            cp_stage(sxa, n, h + 3, w0, tid);
            cp_stage(sxa, n, h + 4, w0, tid);
            asm volatile("cp.async.wait_group 2;" ::: "memory");
        } else {
            asm volatile("cp.async.wait_group 0;" ::: "memory");
        }
        __syncthreads();     // x rows h-1..h+2 (and weights) visible

        if (do_mma) {
            float acc[2][2][4][4];     // [row][mt][nt][e]
#pragma unroll
            for (int r = 0; r < 2; r++)
#pragma unroll
                for (int mt = 0; mt < 2; mt++)
#pragma unroll
                    for (int nt = 0; nt < 4; nt++)
#pragma unroll
                        for (int e = 0; e < 4; e++) acc[r][mt][nt][e] = 0.0f;

            // x-row xr covers: row0 (out h) with kh=xr (xr<3), row1 (out h+1) with kh=xr-1 (xr>0)
#pragma unroll
            for (int xr = 0; xr < 4; xr++) {
                const uint32_t* slotp = sx + ((h - 1 + xr + NSLOT) & (NSLOT - 1)) * SLOTU;
#pragma unroll
                for (int kw = 0; kw < 3; kw++) {
                    const uint32_t* ap_base = slotp + tc * PXS + 3 + colb + kw + gr;
#pragma unroll
                    for (int ks = 0; ks < 4; ks++) {
                        const uint32_t* ap = ap_base + (8 * ks) * PXS;
                        uint32_t A[2][4];
#pragma unroll
                        for (int mt = 0; mt < 2; mt++) {
                            const uint32_t* a = ap + mt * 16;
                            A[mt][0] = a[0];
                            A[mt][1] = a[8];
                            A[mt][2] = a[4 * PXS];
                            A[mt][3] = a[4 * PXS + 8];
                        }
                        if (xr < 3) {      // row0, tap = xr*3+kw
                            const uint2* bq = B64 +
                                ((((xr * 3 + kw) * 4 + ks) * 8 + wn * 4) * 32 + gr * 4 + tc);
#pragma unroll
                            for (int nt = 0; nt < 4; nt++) {
                                uint2 b = bq[nt * 32];
                                mma_h(acc[0][0][nt], A[0], b.x, b.y);
                                mma_h(acc[0][1][nt], A[1], b.x, b.y);
                            }
                        }
                        if (xr > 0) {      // row1, tap = (xr-1)*3+kw
                            const uint2* bq = B64 +
                                (((((xr - 1) * 3 + kw) * 4 + ks) * 8 + wn * 4) * 32 + gr * 4 + tc);
#pragma unroll
                            for (int nt = 0; nt < 4; nt++) {
                                uint2 b = bq[nt * 32];
                                mma_h(acc[1][0][nt], A[0], b.x, b.y);
                                mma_h(acc[1][1][nt], A[1], b.x, b.y);
                            }
                        }
                    }
                }
            }

            // epilogue: 2 rows
#pragma unroll
            for (int r = 0; r < 2; r++) {
                const int hr = h + r;
#pragma unroll
                for (int mt = 0; mt < 2; mt++) {
#pragma unroll
                    for (int nt = 0; nt < 4; nt++) {
                        int co = wn * 32 + nt * 8 + 2 * tc;
                        int wg = w0 + colb + mt * 16 + gr;
                        float* p = out + ((size_t)(n * C_OUT + co)) * HW + (size_t)hr * Wdim + wg;
                        p[0]      = acc[r][mt][nt][0] * als[nt][0] + bis[nt][0];
                        p[HW]     = acc[r][mt][nt][1] * als[nt][1] + bis[nt][1];
                        p[8]      = acc[r][mt][nt][2] * als[nt][0] + bis[nt][0];
                        p[HW + 8] = acc[r][mt][nt][3] * als[nt][1] + bis[nt][1];
                    }
                }
            }
        }
        // no trailing sync: ring slots written next iter (rows h+5,h+6 -> slots (h-3),(h-2) mod 8)
        // are disjoint from slots read this iter (h-1..h+2), even with 1-iter thread skew.
    }
}

extern "C" void kernel_launch(void* const* d_in, const int* in_sizes, int n_in,
                              void* d_out, int out_size) {
    const float* x      = (const float*)d_in[0];
    const float* weight = (const float*)d_in[1];
    const float* bias   = (const float*)d_in[2];
    float* out          = (float*)d_out;

    cudaFuncSetAttribute(conv_kernel, cudaFuncAttributeMaxDynamicSharedMemorySize,
                         SMEM_TOTAL);

    prepass_kernel<<<16 * 32 * HW / 4 / 256, 256>>>(x);
    ternarize_kernel<<<C_OUT, 256>>>(weight);

    dim3 grid(2, 28, 16);
    conv_kernel<<<grid, NTHR, SMEM_TOTAL>>>(bias, out);
}

// round 11
// speedup vs baseline: 4.4121x; 1.0207x over previous
#include <cuda_runtime.h>
#include <cuda_fp16.h>
#include <cstdint>

#define C_IN   64
#define C_OUT  64
#define Hdim   224
#define Wdim   224
#define HW     (Hdim * Wdim)
#define NTHR   448

// B weight smem: u64 units, index = ((tap*4+ks)*8 + wn*4 + nt)*32 + gr*4 + tc
#define WS_BYTES (9 * 4 * 8 * 32 * 8)   // 73728
#define X_OFF    WS_BYTES
// fp16 x ring: 5 slots x [cipair 32 (stride 232 u32)]; halo j=3 (col -1), interior j=4..227, halo j=228
#define PXS    232
#define SLOTU  (32 * PXS)               // 7424 u32
#define NSLOT  5
#define SMEM_TOTAL (X_OFF + NSLOT * SLOTU * 4)   // 222208 B

// packed fp16 ci-pairs of x: [n][cipair 32][h][w]
__device__ __align__(16) uint32_t g_xh[16 * 32 * HW];
// ternary weights, LDS.64-friendly fragment layout (see ternarize)
__device__ __align__(16) unsigned short g_twB[9 * 4 * 8 * 32 * 4];
__device__ float g_alpha[C_OUT];

// ---------------------------------------------------------------- helpers
__device__ __forceinline__ uint32_t smem_u32(const void* p) {
    uint32_t a;
    asm("{ .reg .u64 t; cvta.to.shared.u64 t, %1; cvt.u32.u64 %0, t; }" : "=r"(a) : "l"(p));
    return a;
}
__device__ __forceinline__ void cp16(uint32_t dst, const void* src, int sz) {
    asm volatile("cp.async.cg.shared.global [%0], [%1], 16, %2;"
                 :: "r"(dst), "l"(src), "r"(sz) : "memory");
}
__device__ __forceinline__ uint32_t packh2(float lo, float hi) {
    return (uint32_t)__half_as_ushort(__float2half_rn(lo)) |
           ((uint32_t)__half_as_ushort(__float2half_rn(hi)) << 16);
}
__device__ __forceinline__ void mma_h(float* c, const uint32_t* a, uint32_t b0, uint32_t b1) {
    asm volatile(
        "mma.sync.aligned.m16n8k16.row.col.f32.f16.f16.f32 "
        "{%0,%1,%2,%3}, {%4,%5,%6,%7}, {%8,%9}, {%0,%1,%2,%3};"
        : "+f"(c[0]), "+f"(c[1]), "+f"(c[2]), "+f"(c[3])
        : "r"(a[0]), "r"(a[1]), "r"(a[2]), "r"(a[3]), "r"(b0), "r"(b1));
}

// ---------------------------------------------------------------- prepass: f32 -> packed fp16 pairs
__global__ void __launch_bounds__(256) prepass_kernel(const float* __restrict__ x) {
    int idx = blockIdx.x * 256 + threadIdx.x;
    int u = idx * 4;
    int n = u / (32 * HW);
    int r = u - n * (32 * HW);
    int c = r / HW;
    int p = r - c * HW;
    const float4 a = *(const float4*)(x + ((size_t)(n * 64 + 2 * c) * HW + p));
    const float4 b = *(const float4*)(x + ((size_t)(n * 64 + 2 * c + 1) * HW + p));
    uint4 o;
    o.x = packh2(a.x, b.x);
    o.y = packh2(a.y, b.y);
    o.z = packh2(a.z, b.z);
    o.w = packh2(a.w, b.w);
    *(uint4*)(g_xh + u) = o;
}

// ---------------------------------------------------------------- ternarize
__global__ void ternarize_kernel(const float* __restrict__ weight) {
    __shared__ float red[256], red2[256];
    __shared__ float s_delta, s_alpha;
    const int co = blockIdx.x, tid = threadIdx.x;
    const float* w = weight + co * 576;

    float v0 = (tid < 576) ? w[tid] : 0.0f;
    float v1 = (tid + 256 < 576) ? w[tid + 256] : 0.0f;
    float v2 = (tid + 512 < 576) ? w[tid + 512] : 0.0f;
    float a0 = fabsf(v0), a1 = fabsf(v1), a2 = fabsf(v2);

    red[tid] = a0 + a1 + a2;
    __syncthreads();
    for (int s = 128; s > 0; s >>= 1) { if (tid < s) red[tid] += red[tid + s]; __syncthreads(); }
    if (tid == 0) s_delta = (float)(0.7 / 576.0) * red[0];
    __syncthreads();
    const float delta = s_delta;

    float m0 = (a0 > delta) ? 1.f : 0.f, m1 = (a1 > delta) ? 1.f : 0.f, m2 = (a2 > delta) ? 1.f : 0.f;
    red[tid] = m0 * a0 + m1 * a1 + m2 * a2;
    red2[tid] = m0 + m1 + m2;
    __syncthreads();
    for (int s = 128; s > 0; s >>= 1) {
        if (tid < s) { red[tid] += red[tid + s]; red2[tid] += red2[tid + s]; }
        __syncthreads();
    }
    if (tid == 0) {
        float cnt = red2[0]; if (cnt < 0.5f) cnt = 1.0f;
        s_alpha = fmaxf(red[0] / cnt, 1e-4f);
        g_alpha[co] = s_alpha;
    }
    __syncthreads();

    const int wn = co >> 5, nt = (co >> 3) & 3, grb = co & 7;
#pragma unroll
    for (int q = 0; q < 3; q++) {
        int f = tid + q * 256;
        if (f < 576) {
            float v = (q == 0) ? v0 : (q == 1) ? v1 : v2;
            float t = (v > delta) ? 1.0f : ((v < -delta) ? -1.0f : 0.0f);
            int ci = f / 9, tap = f % 9;     // weight layout [co][ci][kh][kw]
            int ks = ci >> 4, r = ci & 15;
            int word = r >> 3, rr = r & 7;
            int tcb = rr >> 1, e = rr & 1;
            int u64idx = (((tap * 4 + ks) * 8 + wn * 4 + nt) * 32) + grb * 4 + tcb;
            g_twB[u64idx * 4 + word * 2 + e] = __half_as_ushort(__float2half_rn(t));
        }
    }
}

// ---------------------------------------------------------------- row staging (cp.async interior only)
// 32 cipairs x 56 chunks (224 cols / 4) = 1792 chunks = 4 per thread
__device__ __forceinline__ void cp_stage(uint32_t sxa, int n, int row, int tid) {
    const bool rok = (unsigned)row < (unsigned)Hdim;
    const int srow = rok ? row : 0;
    const int sz16 = rok ? 16 : 0;
    const uint32_t slot_b = sxa + (uint32_t)((row + NSLOT * 2) % NSLOT) * (SLOTU * 4);
    const uint32_t* xb = g_xh + (size_t)n * 32 * HW + (size_t)srow * Wdim;
#pragma unroll
    for (int k = 0; k < 4; k++) {
        int idx = tid + k * NTHR;            // 0..1791
        int c = idx / 56;                    // cipair 0..31
        int q = (idx - c * 56) * 4;          // col 0..220
        cp16(slot_b + (uint32_t)(c * PXS + 4 + q) * 4,
             xb + (size_t)c * HW + q, sz16);
    }
    asm volatile("cp.async.commit_group;" ::: "memory");
}

// ---------------------------------------------------------------- conv
// grid (28, 16). 448 thr = 14 warps: 7 M-warps (32 px, full 224 row) x 2 N-warps (32 co).
// One output row per iteration; 8 rows per CTA.
__global__ void __launch_bounds__(NTHR, 1)
conv_kernel(const float* __restrict__ bias, float* __restrict__ out) {
    extern __shared__ char smem[];
    const uint2* B64 = (const uint2*)smem;
    uint32_t* sx = (uint32_t*)(smem + X_OFF);
    const uint32_t wsa = smem_u32(smem);
    const uint32_t sxa = smem_u32(smem + X_OFF);

    const int tid = threadIdx.x, lane = tid & 31, wid = tid >> 5;
    const int gr = lane >> 2, tc = lane & 3;
    const int wm = (wid < 7) ? wid : wid - 7;
    const int wn = (wid < 7) ? 0 : 1;
    const int colb = wm * 32;
    const int h0 = blockIdx.x * 8;
    const int n  = blockIdx.y;

    // boundary halos (cols -1 and 224) are always zero: init once, all slots
    for (int idx = tid; idx < NSLOT * 64; idx += NTHR) {
        int slot = idx >> 6;
        int c = (idx & 63) >> 1, side = idx & 1;
        sx[slot * SLOTU + c * PXS + 3 + side * 225] = 0;
    }

    // weights -> smem, straight copy: 4608 chunks of 16B
    {
#pragma unroll
        for (int k = 0; k < 11; k++) {
            int chunk = tid + k * NTHR;
            if (chunk < 4608)
                cp16(wsa + (uint32_t)chunk * 16, (const char*)g_twB + (size_t)chunk * 16, 16);
        }
        asm volatile("cp.async.commit_group;" ::: "memory");
    }

    float als[4][2], bis[4][2];
#pragma unroll
    for (int nt = 0; nt < 4; nt++) {
        int co = wn * 32 + nt * 8 + 2 * tc;
        als[nt][0] = g_alpha[co];     als[nt][1] = g_alpha[co + 1];
        bis[nt][0] = bias[co];        bis[nt][1] = bias[co + 1];
    }

    cp_stage(sxa, n, h0 - 1, tid);
    cp_stage(sxa, n, h0,     tid);
    cp_stage(sxa, n, h0 + 1, tid);

    for (int it = 0; it < 8; it++) {
        const int h = h0 + it;
        if (it < 7) {
            cp_stage(sxa, n, h + 2, tid);
            asm volatile("cp.async.wait_group 1;" ::: "memory");
        } else {
            asm volatile("cp.async.wait_group 0;" ::: "memory");
        }
        __syncthreads();     // rows h-1..h+1 (and weights) visible

        float acc[2][4][4];
#pragma unroll
        for (int mt = 0; mt < 2; mt++)
#pragma unroll
            for (int nt = 0; nt < 4; nt++)
#pragma unroll
                for (int e = 0; e < 4; e++) acc[mt][nt][e] = 0.0f;

#pragma unroll
        for (int kh = 0; kh < 3; kh++) {
            const uint32_t* slotp = sx + ((h + kh - 1 + NSLOT * 2) % NSLOT) * SLOTU;
#pragma unroll
            for (int kw = 0; kw < 3; kw++) {
                const uint32_t* ap_base = slotp + tc * PXS + 3 + colb + kw + gr;
                const uint2* bq0 = B64 + ((((kh * 3 + kw) * 4) * 8 + wn * 4) * 32 + gr * 4 + tc);
#pragma unroll
                for (int ks = 0; ks < 4; ks++) {
                    const uint32_t* ap = ap_base + (8 * ks) * PXS;
                    const uint2* bq = bq0 + ks * 256;
                    uint32_t A[2][4];
#pragma unroll
                    for (int mt = 0; mt < 2; mt++) {
                        const uint32_t* a = ap + mt * 16;
                        A[mt][0] = a[0];
                        A[mt][1] = a[8];
                        A[mt][2] = a[4 * PXS];
                        A[mt][3] = a[4 * PXS + 8];
                    }
#pragma unroll
                    for (int nt = 0; nt < 4; nt++) {
                        uint2 b = bq[nt * 32];
                        mma_h(acc[0][nt], A[0], b.x, b.y);
                        mma_h(acc[1][nt], A[1], b.x, b.y);
                    }
                }
            }
        }

        // epilogue
#pragma unroll
        for (int mt = 0; mt < 2; mt++) {
#pragma unroll
            for (int nt = 0; nt < 4; nt++) {
                int co = wn * 32 + nt * 8 + 2 * tc;
                int wg = colb + mt * 16 + gr;
                float* p = out + ((size_t)(n * C_OUT + co)) * HW + (size_t)h * Wdim + wg;
                p[0]      = acc[mt][nt][0] * als[nt][0] + bis[nt][0];
                p[HW]     = acc[mt][nt][1] * als[nt][1] + bis[nt][1];
                p[8]      = acc[mt][nt][2] * als[nt][0] + bis[nt][0];
                p[HW + 8] = acc[mt][nt][3] * als[nt][1] + bis[nt][1];
            }
        }
        // no trailing sync needed: next iter writes slot (h+3)%5 ≡ (h-2)%5, disjoint
        // from rows h-1..h+1 read here, and skew is bounded by the per-iter sync.
    }
}

extern "C" void kernel_launch(void* const* d_in, const int* in_sizes, int n_in,
                              void* d_out, int out_size) {
    const float* x      = (const float*)d_in[0];
    const float* weight = (const float*)d_in[1];
    const float* bias   = (const float*)d_in[2];
    float* out          = (float*)d_out;

    cudaFuncSetAttribute(conv_kernel, cudaFuncAttributeMaxDynamicSharedMemorySize,
                         SMEM_TOTAL);

    prepass_kernel<<<16 * 32 * HW / 4 / 256, 256>>>(x);
    ternarize_kernel<<<C_OUT, 256>>>(weight);

    dim3 grid(28, 16);
    conv_kernel<<<grid, NTHR, SMEM_TOTAL>>>(bias, out);
}

// round 12
// speedup vs baseline: 4.4465x; 1.0078x over previous
#include <cuda_runtime.h>
#include <cuda_fp16.h>
#include <cstdint>

#define C_IN   64
#define C_OUT  64
#define Hdim   224
#define Wdim   224
#define HW     (Hdim * Wdim)
#define NTHR   448

// B weight smem: u64 units, index = ((tap*4+ks)*8 + wn*4 + nt)*32 + gr*4 + tc
#define WS_BYTES (9 * 4 * 8 * 32 * 8)   // 73728
#define X_OFF    WS_BYTES
// fp16 x ring: 5 slots x [cipair 32 (stride 232 u32)]; halo j=3 (col -1), interior j=4..227, halo j=228
#define PXS    232
#define SLOTU  (32 * PXS)               // 7424 u32
#define NSLOT  5
#define SMEM_TOTAL (X_OFF + NSLOT * SLOTU * 4)   // 222208 B

// packed fp16 ci-pairs of x: [n][cipair 32][h][w]
__device__ __align__(16) uint32_t g_xh[16 * 32 * HW];
// ternary weights, LDS.64-friendly fragment layout (see ternarize)
__device__ __align__(16) unsigned short g_twB[9 * 4 * 8 * 32 * 4];
__device__ float g_alpha[C_OUT];

// ---------------------------------------------------------------- helpers
__device__ __forceinline__ uint32_t smem_u32(const void* p) {
    uint32_t a;
    asm("{ .reg .u64 t; cvta.to.shared.u64 t, %1; cvt.u32.u64 %0, t; }" : "=r"(a) : "l"(p));
    return a;
}
__device__ __forceinline__ void cp16(uint32_t dst, const void* src, int sz) {
    asm volatile("cp.async.cg.shared.global [%0], [%1], 16, %2;"
                 :: "r"(dst), "l"(src), "r"(sz) : "memory");
}
__device__ __forceinline__ uint32_t packh2(float lo, float hi) {
    return (uint32_t)__half_as_ushort(__float2half_rn(lo)) |
           ((uint32_t)__half_as_ushort(__float2half_rn(hi)) << 16);
}
__device__ __forceinline__ void mma_h(float* c, const uint32_t* a, uint32_t b0, uint32_t b1) {
    asm volatile(
        "mma.sync.aligned.m16n8k16.row.col.f32.f16.f16.f32 "
        "{%0,%1,%2,%3}, {%4,%5,%6,%7}, {%8,%9}, {%0,%1,%2,%3};"
        : "+f"(c[0]), "+f"(c[1]), "+f"(c[2]), "+f"(c[3])
        : "r"(a[0]), "r"(a[1]), "r"(a[2]), "r"(a[3]), "r"(b0), "r"(b1));
}

// ---------------------------------------------------------------- prepass: f32 -> packed fp16 pairs
__global__ void __launch_bounds__(256) prepass_kernel(const float* __restrict__ x) {
    int idx = blockIdx.x * 256 + threadIdx.x;
    int u = idx * 4;
    int n = u / (32 * HW);
    int r = u - n * (32 * HW);
    int c = r / HW;
    int p = r - c * HW;
    const float4 a = *(const float4*)(x + ((size_t)(n * 64 + 2 * c) * HW + p));
    const float4 b = *(const float4*)(x + ((size_t)(n * 64 + 2 * c + 1) * HW + p));
    uint4 o;
    o.x = packh2(a.x, b.x);
    o.y = packh2(a.y, b.y);
    o.z = packh2(a.z, b.z);
    o.w = packh2(a.w, b.w);
    *(uint4*)(g_xh + u) = o;
}

// ---------------------------------------------------------------- ternarize
__global__ void ternarize_kernel(const float* __restrict__ weight) {
    __shared__ float red[256], red2[256];
    __shared__ float s_delta, s_alpha;
    const int co = blockIdx.x, tid = threadIdx.x;
    const float* w = weight + co * 576;

    float v0 = (tid < 576) ? w[tid] : 0.0f;
    float v1 = (tid + 256 < 576) ? w[tid + 256] : 0.0f;
    float v2 = (tid + 512 < 576) ? w[tid + 512] : 0.0f;
    float a0 = fabsf(v0), a1 = fabsf(v1), a2 = fabsf(v2);

    red[tid] = a0 + a1 + a2;
    __syncthreads();
    for (int s = 128; s > 0; s >>= 1) { if (tid < s) red[tid] += red[tid + s]; __syncthreads(); }
    if (tid == 0) s_delta = (float)(0.7 / 576.0) * red[0];
    __syncthreads();
    const float delta = s_delta;

    float m0 = (a0 > delta) ? 1.f : 0.f, m1 = (a1 > delta) ? 1.f : 0.f, m2 = (a2 > delta) ? 1.f : 0.f;
    red[tid] = m0 * a0 + m1 * a1 + m2 * a2;
    red2[tid] = m0 + m1 + m2;
    __syncthreads();
    for (int s = 128; s > 0; s >>= 1) {
        if (tid < s) { red[tid] += red[tid + s]; red2[tid] += red2[tid + s]; }
        __syncthreads();
    }
    if (tid == 0) {
        float cnt = red2[0]; if (cnt < 0.5f) cnt = 1.0f;
        s_alpha = fmaxf(red[0] / cnt, 1e-4f);
        g_alpha[co] = s_alpha;
    }
    __syncthreads();

    const int wn = co >> 5, nt = (co >> 3) & 3, grb = co & 7;
#pragma unroll
    for (int q = 0; q < 3; q++) {
        int f = tid + q * 256;
        if (f < 576) {
            float v = (q == 0) ? v0 : (q == 1) ? v1 : v2;
            float t = (v > delta) ? 1.0f : ((v < -delta) ? -1.0f : 0.0f);
            int ci = f / 9, tap = f % 9;     // weight layout [co][ci][kh][kw]
            int ks = ci >> 4, r = ci & 15;
            int word = r >> 3, rr = r & 7;
            int tcb = rr >> 1, e = rr & 1;
            int u64idx = (((tap * 4 + ks) * 8 + wn * 4 + nt) * 32) + grb * 4 + tcb;
            g_twB[u64idx * 4 + word * 2 + e] = __half_as_ushort(__float2half_rn(t));
        }
    }
}

// ---------------------------------------------------------------- row staging (cp.async interior only)
// 32 cipairs x 56 chunks (224 cols / 4) = 1792 chunks = 4 per thread
__device__ __forceinline__ void cp_stage(uint32_t sxa, int n, int row, int tid) {
    const bool rok = (unsigned)row < (unsigned)Hdim;
    const int srow = rok ? row : 0;
    const int sz16 = rok ? 16 : 0;
    const uint32_t slot_b = sxa + (uint32_t)((row + NSLOT * 2) % NSLOT) * (SLOTU * 4);
    const uint32_t* xb = g_xh + (size_t)n * 32 * HW + (size_t)srow * Wdim;
#pragma unroll
    for (int k = 0; k < 4; k++) {
        int idx = tid + k * NTHR;            // 0..1791
        int c = idx / 56;                    // cipair 0..31
        int q = (idx - c * 56) * 4;          // col 0..220
        cp16(slot_b + (uint32_t)(c * PXS + 4 + q) * 4,
             xb + (size_t)c * HW + q, sz16);
    }
    asm volatile("cp.async.commit_group;" ::: "memory");
}

// ---------------------------------------------------------------- conv (persistent)
// grid (148). 448 thr = 14 warps: 7 M-warps (32 px, full 224 row) x 2 N-warps (32 co).
// Each CTA owns a contiguous chunk of the 3584 flattened (n, h) output rows:
// first 32 CTAs take 25 rows, remaining 116 take 24 (32*25 + 116*24 = 3584).
__global__ void __launch_bounds__(NTHR, 1)
conv_kernel(const float* __restrict__ bias, float* __restrict__ out) {
    extern __shared__ char smem[];
    const uint2* B64 = (const uint2*)smem;
    uint32_t* sx = (uint32_t*)(smem + X_OFF);
    const uint32_t wsa = smem_u32(smem);
    const uint32_t sxa = smem_u32(smem + X_OFF);

    const int tid = threadIdx.x, lane = tid & 31, wid = tid >> 5;
    const int gr = lane >> 2, tc = lane & 3;
    const int wm = (wid < 7) ? wid : wid - 7;
    const int wn = (wid < 7) ? 0 : 1;
    const int colb = wm * 32;
    const int bid = blockIdx.x;

    int rs = (bid < 32) ? bid * 25 : 800 + (bid - 32) * 24;
    int re = rs + ((bid < 32) ? 25 : 24);

    // boundary halos (cols -1 and 224) are always zero: init once, all slots
    for (int idx = tid; idx < NSLOT * 64; idx += NTHR) {
        int slot = idx >> 6;
        int c = (idx & 63) >> 1, side = idx & 1;
        sx[slot * SLOTU + c * PXS + 3 + side * 225] = 0;
    }

    // weights -> smem once: 4608 chunks of 16B
    {
#pragma unroll
        for (int k = 0; k < 11; k++) {
            int chunk = tid + k * NTHR;
            if (chunk < 4608)
                cp16(wsa + (uint32_t)chunk * 16, (const char*)g_twB + (size_t)chunk * 16, 16);
        }
        asm volatile("cp.async.commit_group;" ::: "memory");
    }

    float als[4][2], bis[4][2];
#pragma unroll
    for (int nt = 0; nt < 4; nt++) {
        int co = wn * 32 + nt * 8 + 2 * tc;
        als[nt][0] = g_alpha[co];     als[nt][1] = g_alpha[co + 1];
        bis[nt][0] = bias[co];        bis[nt][1] = bias[co + 1];
    }

    while (rs < re) {
        const int n = rs / Hdim;
        const int h0 = rs - n * Hdim;
        const int hend = min(re - n * Hdim, Hdim);   // rows [h0, hend) of image n

        cp_stage(sxa, n, h0 - 1, tid);
        cp_stage(sxa, n, h0,     tid);
        cp_stage(sxa, n, h0 + 1, tid);

        for (int h = h0; h < hend; h++) {
            if (h + 1 < hend) {
                cp_stage(sxa, n, h + 2, tid);
                asm volatile("cp.async.wait_group 1;" ::: "memory");
            } else {
                asm volatile("cp.async.wait_group 0;" ::: "memory");
            }
            __syncthreads();     // rows h-1..h+1 (and weights) visible

            float acc[2][4][4];
#pragma unroll
            for (int mt = 0; mt < 2; mt++)
#pragma unroll
                for (int nt = 0; nt < 4; nt++)
#pragma unroll
                    for (int e = 0; e < 4; e++) acc[mt][nt][e] = 0.0f;

#pragma unroll
            for (int kh = 0; kh < 3; kh++) {
                const uint32_t* slotp = sx + ((h + kh - 1 + NSLOT * 2) % NSLOT) * SLOTU;
#pragma unroll
                for (int kw = 0; kw < 3; kw++) {
                    const uint32_t* ap_base = slotp + tc * PXS + 3 + colb + kw + gr;
                    const uint2* bq0 = B64 + ((((kh * 3 + kw) * 4) * 8 + wn * 4) * 32 + gr * 4 + tc);
#pragma unroll
                    for (int ks = 0; ks < 4; ks++) {
                        const uint32_t* ap = ap_base + (8 * ks) * PXS;
                        const uint2* bq = bq0 + ks * 256;
                        uint32_t A[2][4];
#pragma unroll
                        for (int mt = 0; mt < 2; mt++) {
                            const uint32_t* a = ap + mt * 16;
                            A[mt][0] = a[0];
                            A[mt][1] = a[8];
                            A[mt][2] = a[4 * PXS];
                            A[mt][3] = a[4 * PXS + 8];
                        }
#pragma unroll
                        for (int nt = 0; nt < 4; nt++) {
                            uint2 b = bq[nt * 32];
                            mma_h(acc[0][nt], A[0], b.x, b.y);
                            mma_h(acc[1][nt], A[1], b.x, b.y);
                        }
                    }
                }
            }

            // epilogue
#pragma unroll
            for (int mt = 0; mt < 2; mt++) {
#pragma unroll
                for (int nt = 0; nt < 4; nt++) {
                    int co = wn * 32 + nt * 8 + 2 * tc;
                    int wg = colb + mt * 16 + gr;
                    float* p = out + ((size_t)(n * C_OUT + co)) * HW + (size_t)h * Wdim + wg;
                    p[0]      = acc[mt][nt][0] * als[nt][0] + bis[nt][0];
                    p[HW]     = acc[mt][nt][1] * als[nt][1] + bis[nt][1];
                    p[8]      = acc[mt][nt][2] * als[nt][0] + bis[nt][0];
                    p[HW + 8] = acc[mt][nt][3] * als[nt][1] + bis[nt][1];
                }
            }
            // intra-loop ring safety: next iter writes slot (h+3)%5 ≡ (h-2)%5,
            // disjoint from rows h-1..h+1 read here; skew bounded by per-iter sync.
        }
        __syncthreads();     // segment end: all reads done before next prime overwrites slots
        rs = n * Hdim + hend;
    }
}

extern "C" void kernel_launch(void* const* d_in, const int* in_sizes, int n_in,
                              void* d_out, int out_size) {
    const float* x      = (const float*)d_in[0];
    const float* weight = (const float*)d_in[1];
    const float* bias   = (const float*)d_in[2];
    float* out          = (float*)d_out;

    cudaFuncSetAttribute(conv_kernel, cudaFuncAttributeMaxDynamicSharedMemorySize,
                         SMEM_TOTAL);

    prepass_kernel<<<16 * 32 * HW / 4 / 256, 256>>>(x);
    ternarize_kernel<<<C_OUT, 256>>>(weight);

    conv_kernel<<<148, NTHR, SMEM_TOTAL>>>(bias, out);
}